// round 17
// baseline (speedup 1.0000x reference)
#include <cuda_runtime.h>
#include <math.h>
#include <stdint.h>

// ---------------- problem constants ----------------
constexpr int Bc   = 2;
constexpr int Sc   = 2048;
constexpr int Hc   = 2048;
constexpr int Tc   = Bc * Sc;      // 4096 tokens
constexpr int Ec   = 8;
constexpr int IM   = 1408;
constexpr int ISH  = 5632;
constexpr int NQc  = 16;
constexpr int NKVc = 2;
constexpr int DHc  = 128;
constexpr float EPSc = 1e-5f;
constexpr int NQKV = 2560;         // 2048 (Q) + 256 (K) + 256 (V)

// rounded-weight scratch offsets
constexpr size_t OFF_QKV  = 0;                              // [2048][2560]
constexpr size_t OFF_WO   = OFF_QKV  + (size_t)2048 * NQKV;
constexpr size_t OFF_WGU  = OFF_WO   + (size_t)2048 * 2048;  // [E][2048][2816] gate/up interleaved
constexpr size_t OFF_WD   = OFF_WGU  + (size_t)Ec * 2048 * 2 * IM;
constexpr size_t OFF_SWGU = OFF_WD   + (size_t)Ec * IM * 2048; // [2048][11264] interleaved
constexpr size_t OFF_SWD  = OFF_SWGU + (size_t)2048 * 2 * ISH;
constexpr size_t WR_TOT   = OFF_SWD  + (size_t)ISH * 2048;

// ---------------- scratch (device globals; no allocations allowed) ----------------
__device__ float g_wr [WR_TOT];                      // tf32-rounded weights
__device__ float g_bqkv[NQKV];                       // concatenated q/k/v biases
__device__ float g_h  [(size_t)Tc * Hc];
__device__ float g_q  [(size_t)Tc * NQc * DHc];
__device__ float g_k  [(size_t)Tc * NKVc * DHc];
__device__ float g_v  [(size_t)Tc * NKVc * DHc];
__device__ float g_kT [(size_t)Bc * NKVc * DHc * Sc];
__device__ float g_ao [(size_t)Tc * Hc];
__device__ float g_x  [(size_t)Tc * Hc];
__device__ float g_t2 [(size_t)Tc * Hc];             // exact (router/sgate)
__device__ float g_t2r[(size_t)Tc * Hc];             // tf32-rounded (GEMM A)
__device__ float g_dw [Tc * Ec];
__device__ int   g_cnt[Ec];
__device__ int   g_list[Ec * Tc];
__device__ float g_mg [(size_t)Ec * Tc * IM];        // activated expert hidden
__device__ float g_moe[(size_t)Tc * Hc];
__device__ float g_sgv[(size_t)Tc * ISH];            // activated shared hidden
__device__ float g_sgate[Tc];

__device__ __forceinline__ float tf32r(float x) {
    uint32_t u;
    asm("cvt.rna.tf32.f32 %0, %1;" : "=r"(u) : "f"(x));
    return __uint_as_float(u);
}
__device__ __forceinline__ float4 tf32r4(float4 v) {
    v.x = tf32r(v.x); v.y = tf32r(v.y); v.z = tf32r(v.z); v.w = tf32r(v.w);
    return v;
}
__device__ __forceinline__ float silu(float x) {
    return x / (1.f + expf(-x));
}

// ---------------- weight rounding (float4) ----------------
template<size_t OFF>
__global__ void round_copy_kernel(const float* __restrict__ src, int n4) {
    const int i = blockIdx.x * 256 + threadIdx.x;
    if (i < n4)
        ((float4*)(g_wr + OFF))[i] = tf32r4(((const float4*)src)[i]);
}

template<size_t OFF>
__global__ void round_ilv_kernel(const float* __restrict__ srcA,
                                 const float* __restrict__ srcB, int n2) {
    const int i = blockIdx.x * 256 + threadIdx.x;
    if (i < n2) {
        const float2 a = ((const float2*)srcA)[i];
        const float2 b = ((const float2*)srcB)[i];
        float4 o;
        o.x = tf32r(a.x); o.y = tf32r(b.x);
        o.z = tf32r(a.y); o.w = tf32r(b.y);
        ((float4*)(g_wr + OFF))[i] = o;
    }
}

__global__ void round_copy_str_kernel(const float* __restrict__ src, int n4,
                                      int srcN4, int ldDst, int colOff) {
    const int i = blockIdx.x * 256 + threadIdx.x;
    if (i < n4) {
        const int k = i / srcN4, c4 = i % srcN4;
        const float4 v = tf32r4(((const float4*)src)[i]);
        *(float4*)(g_wr + OFF_QKV + (size_t)k * ldDst + colOff + c4 * 4) = v;
    }
}

__global__ void bias_concat_kernel(const float* __restrict__ bq,
                                   const float* __restrict__ bk,
                                   const float* __restrict__ bv) {
    const int i = blockIdx.x * 256 + threadIdx.x;
    if (i < 2048)       g_bqkv[i] = bq[i];
    else if (i < 2304)  g_bqkv[i] = bk[i - 2048];
    else if (i < NQKV)  g_bqkv[i] = bv[i - 2304];
}

// ---------------- small kernels ----------------
__global__ void clear_cnt_kernel() {
    if (threadIdx.x < Ec) g_cnt[threadIdx.x] = 0;
}
__global__ void clear_moe_kernel() {
    ((float4*)g_moe)[(size_t)blockIdx.x * 256 + threadIdx.x] =
        make_float4(0.f, 0.f, 0.f, 0.f);
}

template<int PHASE>
__global__ void rmsnorm_kernel(const float* __restrict__ xin,
                               const float* __restrict__ scale) {
    __shared__ float red[256];
    const int row = blockIdx.x;
    const float* x = (PHASE == 0) ? (xin + (size_t)row * Hc) : (g_x + (size_t)row * Hc);
    const int tid = threadIdx.x;
    float4 v[2];
    float s = 0.f;
#pragma unroll
    for (int g = 0; g < 2; g++) {
        v[g] = ((const float4*)x)[tid + g * 256];
        s += v[g].x * v[g].x + v[g].y * v[g].y + v[g].z * v[g].z + v[g].w * v[g].w;
    }
    red[tid] = s; __syncthreads();
    for (int o = 128; o > 0; o >>= 1) {
        if (tid < o) red[tid] += red[tid + o];
        __syncthreads();
    }
    const float inv = rsqrtf(red[0] / (float)Hc + EPSc);
#pragma unroll
    for (int g = 0; g < 2; g++) {
        const int j = tid + g * 256;
        const float4 sc4 = ((const float4*)scale)[j];
        float4 o4;
        o4.x = v[g].x * inv * sc4.x;
        o4.y = v[g].y * inv * sc4.y;
        o4.z = v[g].z * inv * sc4.z;
        o4.w = v[g].w * inv * sc4.w;
        if (PHASE == 0) {
            ((float4*)(g_h + (size_t)row * Hc))[j] = tf32r4(o4);
        } else {
            ((float4*)(g_t2  + (size_t)row * Hc))[j] = o4;
            ((float4*)(g_t2r + (size_t)row * Hc))[j] = tf32r4(o4);
        }
    }
}

__global__ void rope_kernel() {
    const int tok  = blockIdx.x;
    const int head = blockIdx.y;
    const int j    = threadIdx.x;         // 0..63
    const int s    = tok & (Sc - 1);
    const float inv = powf(10000.f, -(float)(2 * j) / 128.f);
    const float ang = (float)s * inv;
    float si, c;
    sincosf(ang, &si, &c);
    float* p = (head < NQc) ? (g_q + (size_t)tok * (NQc * DHc) + head * DHc)
                            : (g_k + (size_t)tok * (NKVc * DHc) + (head - NQc) * DHc);
    const float x1 = p[j], x2 = p[j + 64];
    p[j]      = tf32r(x1 * c - x2 * si);
    p[j + 64] = tf32r(x2 * c + x1 * si);
}

__global__ void kT_kernel() {
    const int i  = blockIdx.x * 256 + threadIdx.x;
    const int s  = i & (Sc - 1);
    const int d  = (i >> 11) & 127;
    const int bk = i >> 18;
    g_kT[i] = g_k[((size_t)((bk >> 1) * Sc + s)) * (NKVc * DHc) + (bk & 1) * DHc + d];
}

__global__ void router_kernel(const float* __restrict__ rw) {
    const int tok  = blockIdx.x * 8 + (threadIdx.x >> 5);
    const int lane = threadIdx.x & 31;
    const float* tr = g_t2 + (size_t)tok * Hc;
    float acc[8];
#pragma unroll
    for (int e = 0; e < 8; e++) acc[e] = 0.f;
    for (int h = lane; h < Hc; h += 32) {
        const float tv = tr[h];
        const float* rp = rw + h * 8;
#pragma unroll
        for (int e = 0; e < 8; e++) acc[e] += tv * rp[e];
    }
#pragma unroll
    for (int e = 0; e < 8; e++)
        for (int o = 16; o; o >>= 1) acc[e] += __shfl_xor_sync(0xffffffffu, acc[e], o);
    if (lane == 0) {
        float m = acc[0];
        for (int e = 1; e < 8; e++) m = fmaxf(m, acc[e]);
        float p[8], s = 0.f;
        for (int e = 0; e < 8; e++) { p[e] = expf(acc[e] - m); s += p[e]; }
        for (int e = 0; e < 8; e++) p[e] /= s;
        bool used[8] = {false,false,false,false,false,false,false,false};
        int isel[4]; float wsel[4]; float tsum = 0.f;
        for (int kk = 0; kk < 4; kk++) {
            int best = 0; float bv = -1.f;
            for (int e = 0; e < 8; e++)
                if (!used[e] && p[e] > bv) { bv = p[e]; best = e; }
            used[best] = true; isel[kk] = best; wsel[kk] = bv; tsum += bv;
        }
        float outw[8] = {0,0,0,0,0,0,0,0};
        for (int kk = 0; kk < 4; kk++) outw[isel[kk]] = wsel[kk] / tsum;
        for (int e = 0; e < 8; e++) g_dw[tok * 8 + e] = outw[e];
        for (int kk = 0; kk < 4; kk++) {
            const int pos = atomicAdd(&g_cnt[isel[kk]], 1);
            g_list[isel[kk] * Tc + pos] = tok;
        }
    }
}

__global__ void sgate_kernel(const float* __restrict__ sgw) {
    const int tok  = blockIdx.x * 8 + (threadIdx.x >> 5);
    const int lane = threadIdx.x & 31;
    const float* tr = g_t2 + (size_t)tok * Hc;
    float s = 0.f;
    for (int h = lane; h < Hc; h += 32) s += tr[h] * sgw[h];
    for (int o = 16; o; o >>= 1) s += __shfl_xor_sync(0xffffffffu, s, o);
    if (lane == 0) g_sgate[tok] = 1.f / (1.f + expf(-s));
}

// ---------------- shared PTX helpers ----------------
__device__ __forceinline__ void mma_tf32(float* c, const uint32_t* a, const uint32_t* b) {
    asm volatile(
        "mma.sync.aligned.m16n8k8.row.col.f32.tf32.tf32.f32 "
        "{%0,%1,%2,%3}, {%4,%5,%6,%7}, {%8,%9}, {%0,%1,%2,%3};"
        : "+f"(c[0]), "+f"(c[1]), "+f"(c[2]), "+f"(c[3])
        : "r"(a[0]), "r"(a[1]), "r"(a[2]), "r"(a[3]), "r"(b[0]), "r"(b[1]));
}

__device__ __forceinline__ void ldsm4(uint32_t& r0, uint32_t& r1, uint32_t& r2, uint32_t& r3,
                                      uint32_t addr) {
    asm volatile("ldmatrix.sync.aligned.m8n8.x4.shared.b16 {%0,%1,%2,%3}, [%4];"
                 : "=r"(r0), "=r"(r1), "=r"(r2), "=r"(r3) : "r"(addr));
}

__device__ __forceinline__ void cpa16(uint32_t dst, const void* src, int sz) {
    asm volatile("cp.async.cg.shared.global [%0], [%1], 16, %2;\n"
                 :: "r"(dst), "l"(src), "r"(sz));
}
__device__ __forceinline__ void cpa_commit() {
    asm volatile("cp.async.commit_group;\n");
}
__device__ __forceinline__ void cpa_wait0() {
    asm volatile("cp.async.wait_group 0;\n" ::: "memory");
}
__device__ __forceinline__ void cpa_wait1() {
    asm volatile("cp.async.wait_group 1;\n" ::: "memory");
}

// ---------------- fused flash attention ----------------
constexpr int FQS = 132;
constexpr int FKS = 72;
constexpr int FVS = 136;
constexpr int FPS = 68;
constexpr int F_K0 = 128 * FQS;
constexpr int F_V0 = F_K0 + 2 * 128 * FKS;
constexpr int F_P0 = F_V0 + 64 * FVS;
constexpr int FSMEM = (F_P0 + 128 * FPS) * 4;

__global__ __launch_bounds__(256, 1) void flash_kernel() {
    extern __shared__ float fs[];
    const int tid = threadIdx.x, lane = tid & 31, wid = tid >> 5;
    const int z  = blockIdx.z;
    const int qt = 15 - blockIdx.y;
    const int bb = z >> 4, hh = z & 15;
    const int q0 = qt * 128;
    const int nc = 2 * qt + 2;
    const float scl = 0.08838834764831845f;

    const uint32_t sb = (uint32_t)__cvta_generic_to_shared(fs);
    const uint32_t sQ = sb, sK = sb + F_K0 * 4, sV = sb + F_V0 * 4, sP = sb + F_P0 * 4;
    float* Ksf = fs + F_K0;
    float* Vsf = fs + F_V0;
    float* Psf = fs + F_P0;

    const float* Qg  = g_q + ((size_t)bb * Sc + q0) * 2048 + hh * 128;
    const float* KTg = g_kT + (size_t)(bb * 2 + (hh >> 3)) * 128 * Sc;
    const float* Vg  = g_v + (size_t)bb * Sc * 256 + (hh >> 3) * 128;

    {
        const int r = tid >> 1, hf = tid & 1;
#pragma unroll
        for (int c = 0; c < 16; c++)
            cpa16(sQ + (uint32_t)(r * FQS + hf * 64 + c * 4) * 4,
                  Qg + (size_t)r * 2048 + hf * 64 + c * 4, 16);
#pragma unroll
        for (int c = 0; c < 8; c++)
            cpa16(sK + (uint32_t)(r * FKS + hf * 32 + c * 4) * 4,
                  KTg + (size_t)r * Sc + hf * 32 + c * 4, 16);
    }
    cpa_commit();

    float oacc[16][4];
#pragma unroll
    for (int j = 0; j < 16; j++)
#pragma unroll
        for (int e = 0; e < 4; e++) oacc[j][e] = 0.f;
    float mrow[2] = {-1e30f, -1e30f};
    float lrow[2] = {0.f, 0.f};

    const int wm = wid * 16;
    const int kq = lane & 3, cbq = lane >> 2;
    const int lrw = lane & 15, lcl = (lane >> 4) << 2;

    for (int c = 0; c < nc; c++) {
        const int kc0 = c * 64;
        const int kbuf = c & 1;
        cpa_wait0();
        __syncthreads();

        {
            const int r = tid >> 2, q4 = tid & 3;
#pragma unroll
            for (int cc = 0; cc < 8; cc++)
                cpa16(sV + (uint32_t)(r * FVS + q4 * 32 + cc * 4) * 4,
                      Vg + (size_t)(kc0 + r) * 256 + q4 * 32 + cc * 4, 16);
        }
        cpa_commit();
        const bool more = (c + 1) < nc;
        if (more) {
            const int r = tid >> 1, hf = tid & 1;
            const int nb = (c + 1) & 1;
#pragma unroll
            for (int cc = 0; cc < 8; cc++)
                cpa16(sK + (uint32_t)((nb * 128 + r) * FKS + hf * 32 + cc * 4) * 4,
                      KTg + (size_t)r * Sc + (kc0 + 64) + hf * 32 + cc * 4, 16);
            cpa_commit();
        }

        float sacc[8][4];
#pragma unroll
        for (int j = 0; j < 8; j++)
#pragma unroll
            for (int e = 0; e < 4; e++) sacc[j][e] = 0.f;

#pragma unroll
        for (int ks = 0; ks < 16; ks++) {
            uint32_t af[4];
            ldsm4(af[0], af[1], af[2], af[3],
                  sQ + (uint32_t)((wm + lrw) * FQS + ks * 8 + lcl) * 4);
            const float* kb = Ksf + (size_t)kbuf * 128 * FKS;
#pragma unroll
            for (int j = 0; j < 8; j++) {
                uint32_t bf[2];
                bf[0] = __float_as_uint(kb[(ks * 8 + kq) * FKS + cbq + j * 8]);
                bf[1] = __float_as_uint(kb[(ks * 8 + kq + 4) * FKS + cbq + j * 8]);
                mma_tf32(sacc[j], af, bf);
            }
        }

#pragma unroll
        for (int mi = 0; mi < 2; mi++) {
            const int rg = q0 + wm + (lane >> 2) + mi * 8;
            float mx = -1e30f;
#pragma unroll
            for (int j = 0; j < 8; j++)
#pragma unroll
                for (int e = 0; e < 2; e++) {
                    const int cg = kc0 + (lane & 3) * 2 + j * 8 + e;
                    float v = (cg <= rg) ? sacc[j][mi * 2 + e] * scl : -1e30f;
                    sacc[j][mi * 2 + e] = v;
                    mx = fmaxf(mx, v);
                }
            mx = fmaxf(mx, __shfl_xor_sync(0xffffffffu, mx, 1));
            mx = fmaxf(mx, __shfl_xor_sync(0xffffffffu, mx, 2));
            const float newm = fmaxf(mrow[mi], mx);
            const float sc2 = expf(mrow[mi] - newm);
            float rs = 0.f;
#pragma unroll
            for (int j = 0; j < 8; j++)
#pragma unroll
                for (int e = 0; e < 2; e++) {
                    const float p = expf(sacc[j][mi * 2 + e] - newm);
                    sacc[j][mi * 2 + e] = p;
                    rs += p;
                }
            rs += __shfl_xor_sync(0xffffffffu, rs, 1);
            rs += __shfl_xor_sync(0xffffffffu, rs, 2);
            lrow[mi] = lrow[mi] * sc2 + rs;
            mrow[mi] = newm;
#pragma unroll
            for (int j = 0; j < 16; j++) {
                oacc[j][mi * 2 + 0] *= sc2;
                oacc[j][mi * 2 + 1] *= sc2;
            }
            const int pr = wm + (lane >> 2) + mi * 8;
#pragma unroll
            for (int j = 0; j < 8; j++) {
                Psf[pr * FPS + (lane & 3) * 2 + j * 8 + 0] = tf32r(sacc[j][mi * 2 + 0]);
                Psf[pr * FPS + (lane & 3) * 2 + j * 8 + 1] = tf32r(sacc[j][mi * 2 + 1]);
            }
        }

        if (more) cpa_wait1(); else cpa_wait0();
        __syncthreads();

#pragma unroll
        for (int ks = 0; ks < 8; ks++) {
            uint32_t af[4];
            ldsm4(af[0], af[1], af[2], af[3],
                  sP + (uint32_t)((wm + lrw) * FPS + ks * 8 + lcl) * 4);
#pragma unroll
            for (int j = 0; j < 16; j++) {
                uint32_t bf[2];
                bf[0] = __float_as_uint(Vsf[(ks * 8 + kq) * FVS + cbq + j * 8]);
                bf[1] = __float_as_uint(Vsf[(ks * 8 + kq + 4) * FVS + cbq + j * 8]);
                mma_tf32(oacc[j], af, bf);
            }
        }
        __syncthreads();
    }

#pragma unroll
    for (int mi = 0; mi < 2; mi++) {
        const float inv = 1.f / lrow[mi];
        const int rg = q0 + wm + (lane >> 2) + mi * 8;
        float* dst = g_ao + ((size_t)bb * Sc + rg) * 2048 + hh * 128;
#pragma unroll
        for (int j = 0; j < 16; j++) {
            dst[(lane & 3) * 2 + j * 8 + 0] = tf32r(oacc[j][mi * 2 + 0] * inv);
            dst[(lane & 3) * 2 + j * 8 + 1] = tf32r(oacc[j][mi * 2 + 1] * inv);
        }
    }
}

// ---------------- tf32 GEMM: BK=32, 3-stage cp.async + ldmatrix-A ----------------
enum GMode { GM_QKV, GM_O, GM_MGU, GM_MD, GM_SGU, GM_SD };

constexpr int AST = 36;                   // A stride (floats) for BK=32
constexpr int BST = 136;                  // B stride (floats)
constexpr int A_STG = 128 * AST;          // 4608 floats
constexpr int B_STG = 32 * BST;           // 4352 floats
constexpr int GSMEM = 3 * (A_STG + B_STG) * 4;   // 107520 bytes

template<int MODE>
__global__ __launch_bounds__(128, 2) void gemm_kernel(const float* __restrict__ extra) {
    extern __shared__ float smem[];
    constexpr int Kv = (MODE==GM_MD) ? IM : (MODE==GM_SD) ? ISH : 2048;

    const int tid = threadIdx.x;
    const int z   = blockIdx.z;
    const int m0  = blockIdx.y * 128, n0 = blockIdx.x * 128;

    int Mz;
    if (MODE==GM_MGU || MODE==GM_MD) Mz = g_cnt[z];
    else Mz = Tc;
    if (m0 >= Mz) return;

    const float* A; const float* Bp; int lda, ldb;
    if (MODE==GM_QKV) {
        A = g_h; lda = Hc; Bp = g_wr + OFF_QKV; ldb = NQKV;
    } else if (MODE==GM_O) {
        A = g_ao; lda = 2048; Bp = g_wr + OFF_WO; ldb = 2048;
    } else if (MODE==GM_MGU) {
        A = g_t2r; lda = 2048; Bp = g_wr + OFF_WGU + (size_t)z * 2048 * 2 * IM; ldb = 2 * IM;
    } else if (MODE==GM_MD) {
        A = g_mg + (size_t)z * Tc * IM; lda = IM;
        Bp = g_wr + OFF_WD + (size_t)z * IM * 2048; ldb = 2048;
    } else if (MODE==GM_SGU) {
        A = g_t2r; lda = 2048; Bp = g_wr + OFF_SWGU; ldb = 2 * ISH;
    } else { // GM_SD
        A = g_sgv; lda = ISH; Bp = g_wr + OFF_SWD; ldb = 2048;
    }

    float* Asf = smem;
    float* Bsf = smem + 3 * A_STG;

    float acc[4][8][4];
#pragma unroll
    for (int i = 0; i < 4; i++)
#pragma unroll
        for (int j = 0; j < 8; j++)
#pragma unroll
            for (int r = 0; r < 4; r++) acc[i][j][r] = 0.f;

    const int lane = tid & 31, wid = tid >> 5;
    const int wm = (wid >> 1) * 64;
    const int wn = (wid & 1) * 64;

    const int lm = tid;
    const int agl = m0 + lm;
    const bool aval = agl < Mz;
    const float* arp;
    if (MODE==GM_MGU)
        arp = A + (size_t)(aval ? g_list[z * Tc + agl] : 0) * lda;
    else
        arp = A + (size_t)(aval ? agl : 0) * lda;
    const int asz = aval ? 16 : 0;
    const int arot = (lm >> 3) & 7;

    const int bw = tid >> 5;
    const int bn = (tid & 31) * 4;
    const float* bbase = Bp + n0;

    const int nt = Kv / 32;

    const uint32_t sA = (uint32_t)__cvta_generic_to_shared(Asf);
    const uint32_t sB = (uint32_t)__cvta_generic_to_shared(Bsf);

    auto load_stage = [&](int s, int k0) {
#pragma unroll
        for (int c = 0; c < 8; c++) {
            const int cc = (c + arot) & 7;
            cpa16(sA + (uint32_t)((s * 128 + lm) * AST + cc * 4) * 4, arp + k0 + cc * 4, asz);
        }
#pragma unroll
        for (int c = 0; c < 8; c++) {
            const int k = c * 4 + bw;
            cpa16(sB + (uint32_t)((s * 32 + k) * BST + bn) * 4,
                  bbase + (size_t)(k0 + k) * ldb + bn, 16);
        }
    };

    load_stage(0, 0);
    cpa_commit();
    if (nt > 1) load_stage(1, 32);
    cpa_commit();

    const int cb = wn + (lane >> 2);
    const int kq = lane & 3;
    const int lrow = lane & 15;
    const int lcol = (lane >> 4) << 2;

    int cur = 0, n2 = 2;
    for (int t = 0; t < nt; t++) {
        cpa_wait1();
        __syncthreads();
        if (t + 2 < nt) load_stage(n2, (t + 2) * 32);
        cpa_commit();

#pragma unroll
        for (int ks = 0; ks < 4; ks++) {
            const int klo = ks * 8;
            const int kk = klo + kq;
            uint32_t af[4][4], bf[8][2];
#pragma unroll
            for (int i = 0; i < 4; i++) {
                const uint32_t addr = sA +
                    (uint32_t)((cur * 128 + wm + i * 16 + lrow) * AST + klo + lcol) * 4;
                ldsm4(af[i][0], af[i][1], af[i][2], af[i][3], addr);
            }
#pragma unroll
            for (int j = 0; j < 8; j++) {
                bf[j][0] = __float_as_uint(Bsf[(cur * 32 + kk) * BST + cb + j * 8]);
                bf[j][1] = __float_as_uint(Bsf[(cur * 32 + kk + 4) * BST + cb + j * 8]);
            }
#pragma unroll
            for (int i = 0; i < 4; i++)
#pragma unroll
                for (int j = 0; j < 8; j++)
                    mma_tf32(acc[i][j], af[i], bf[j]);
        }
        cur = (cur == 2) ? 0 : cur + 1;
        n2  = (n2  == 2) ? 0 : n2  + 1;
    }

    // ---------------- epilogues ----------------
#pragma unroll
    for (int i = 0; i < 4; i++) {
#pragma unroll
        for (int rr = 0; rr < 2; rr++) {
            const int r = m0 + wm + i * 16 + (lane >> 2) + rr * 8;
            if (r >= Mz) continue;
            if (MODE==GM_QKV) {
#pragma unroll
                for (int j = 0; j < 8; j++) {
                    const int c = n0 + wn + j * 8 + (lane & 3) * 2;
                    float v0 = acc[i][j][rr * 2 + 0] + g_bqkv[c];
                    float v1 = acc[i][j][rr * 2 + 1] + g_bqkv[c + 1];
                    if (c < 2048) {
                        g_q[(size_t)r * 2048 + c]     = v0;
                        g_q[(size_t)r * 2048 + c + 1] = v1;
                    } else if (c < 2304) {
                        g_k[(size_t)r * 256 + c - 2048]     = v0;
                        g_k[(size_t)r * 256 + c - 2048 + 1] = v1;
                    } else {
                        g_v[(size_t)r * 256 + c - 2304]     = tf32r(v0);
                        g_v[(size_t)r * 256 + c - 2304 + 1] = tf32r(v1);
                    }
                }
            } else if (MODE==GM_MGU) {
                float* dst = g_mg + ((size_t)z * Tc + r) * IM;
#pragma unroll
                for (int j = 0; j < 8; j++) {
                    const int c = n0 + wn + j * 8 + (lane & 3) * 2;
                    const float g0 = acc[i][j][rr * 2 + 0];
                    const float u0 = acc[i][j][rr * 2 + 1];
                    dst[c >> 1] = tf32r(silu(g0) * u0);
                }
            } else if (MODE==GM_SGU) {
                float* dst = g_sgv + (size_t)r * ISH;
#pragma unroll
                for (int j = 0; j < 8; j++) {
                    const int c = n0 + wn + j * 8 + (lane & 3) * 2;
                    const float g0 = acc[i][j][rr * 2 + 0];
                    const float u0 = acc[i][j][rr * 2 + 1];
                    dst[c >> 1] = tf32r(silu(g0) * u0);
                }
            } else if (MODE==GM_MD) {
                const int tok = g_list[z * Tc + r];
                const float w = g_dw[tok * Ec + z];
                float* dst = g_moe + (size_t)tok * 2048;
#pragma unroll
                for (int j = 0; j < 8; j++) {
                    const int c = n0 + wn + j * 8 + (lane & 3) * 2;
                    atomicAdd(dst + c,     acc[i][j][rr * 2 + 0] * w);
                    atomicAdd(dst + c + 1, acc[i][j][rr * 2 + 1] * w);
                }
            } else if (MODE==GM_SD) {
                // fused final: out = x + moe + sgate * sh
                float* outp = (float*)extra;
                const float sg = g_sgate[r];
                const size_t rowoff = (size_t)r * 2048;
#pragma unroll
                for (int j = 0; j < 8; j++) {
                    const int c = n0 + wn + j * 8 + (lane & 3) * 2;
                    outp[rowoff + c] = g_x[rowoff + c] + g_moe[rowoff + c]
                                     + sg * acc[i][j][rr * 2 + 0];
                    outp[rowoff + c + 1] = g_x[rowoff + c + 1] + g_moe[rowoff + c + 1]
                                     + sg * acc[i][j][rr * 2 + 1];
                }
            } else { // GM_O
                float* Cp = g_x;
                const float* res = extra;
                const size_t rowoff = (size_t)r * 2048;
#pragma unroll
                for (int j = 0; j < 8; j++) {
                    const int c = n0 + wn + j * 8 + (lane & 3) * 2;
                    Cp[rowoff + c]     = acc[i][j][rr * 2 + 0] + res[rowoff + c];
                    Cp[rowoff + c + 1] = acc[i][j][rr * 2 + 1] + res[rowoff + c + 1];
                }
            }
        }
    }
}

// ---------------- launch ----------------
extern "C" void kernel_launch(void* const* d_in, const int* in_sizes, int n_in,
                              void* d_out, int out_size) {
    (void)in_sizes; (void)n_in; (void)out_size;
    const float* x0  = (const float*)d_in[0];
    const float* ln1 = (const float*)d_in[1];
    const float* wq  = (const float*)d_in[2];
    const float* bq  = (const float*)d_in[3];
    const float* wk  = (const float*)d_in[4];
    const float* bk  = (const float*)d_in[5];
    const float* wv  = (const float*)d_in[6];
    const float* bv  = (const float*)d_in[7];
    const float* wo  = (const float*)d_in[8];
    const float* ln2 = (const float*)d_in[9];
    const float* rw  = (const float*)d_in[10];
    const float* wg  = (const float*)d_in[11];
    const float* wu  = (const float*)d_in[12];
    const float* wd  = (const float*)d_in[13];
    const float* swg = (const float*)d_in[14];
    const float* swu = (const float*)d_in[15];
    const float* swd = (const float*)d_in[16];
    const float* sgw = (const float*)d_in[17];
    float* out = (float*)d_out;

    cudaFuncSetAttribute(gemm_kernel<GM_QKV>, cudaFuncAttributeMaxDynamicSharedMemorySize, GSMEM);
    cudaFuncSetAttribute(gemm_kernel<GM_O>,   cudaFuncAttributeMaxDynamicSharedMemorySize, GSMEM);
    cudaFuncSetAttribute(gemm_kernel<GM_MGU>, cudaFuncAttributeMaxDynamicSharedMemorySize, GSMEM);
    cudaFuncSetAttribute(gemm_kernel<GM_MD>,  cudaFuncAttributeMaxDynamicSharedMemorySize, GSMEM);
    cudaFuncSetAttribute(gemm_kernel<GM_SGU>, cudaFuncAttributeMaxDynamicSharedMemorySize, GSMEM);
    cudaFuncSetAttribute(gemm_kernel<GM_SD>,  cudaFuncAttributeMaxDynamicSharedMemorySize, GSMEM);
    cudaFuncSetAttribute(flash_kernel,        cudaFuncAttributeMaxDynamicSharedMemorySize, FSMEM);

    auto b4 = [](size_t n) { return (unsigned)((n + 255) / 256); };

    round_copy_str_kernel<<<b4((size_t)2048*512), 256>>>(wq, 2048*512, 512, NQKV, 0);
    round_copy_str_kernel<<<b4((size_t)2048*64),  256>>>(wk, 2048*64,  64,  NQKV, 2048);
    round_copy_str_kernel<<<b4((size_t)2048*64),  256>>>(wv, 2048*64,  64,  NQKV, 2304);
    bias_concat_kernel<<<10, 256>>>(bq, bk, bv);
    round_copy_kernel<OFF_WO ><<<b4((size_t)2048*512), 256>>>(wo, 2048*512);
    round_ilv_kernel<OFF_WGU ><<<b4((size_t)Ec*2048*IM/2), 256>>>(wg, wu, Ec*2048*IM/2);
    round_copy_kernel<OFF_WD ><<<b4((size_t)Ec*IM*512), 256>>>(wd, Ec*IM*512);
    round_ilv_kernel<OFF_SWGU><<<b4((size_t)2048*ISH/2), 256>>>(swg, swu, 2048*ISH/2);
    round_copy_kernel<OFF_SWD><<<b4((size_t)ISH*512), 256>>>(swd, ISH*512);

    clear_cnt_kernel<<<1, 32>>>();
    clear_moe_kernel<<<(Tc * Hc) / 1024, 256>>>();

    // attention
    rmsnorm_kernel<0><<<Tc, 256>>>(x0, ln1);
    gemm_kernel<GM_QKV><<<dim3(20, 32, 1), 128, GSMEM>>>(nullptr);
    rope_kernel<<<dim3(Tc, NQc + NKVc), 64>>>();
    kT_kernel<<<(Bc * NKVc * DHc * Sc) / 256, 256>>>();
    flash_kernel<<<dim3(1, 16, 32), 256, FSMEM>>>();
    gemm_kernel<GM_O><<<dim3(16, 32, 1), 128, GSMEM>>>(x0);

    // MoE block
    rmsnorm_kernel<1><<<Tc, 256>>>(nullptr, ln2);
    router_kernel<<<Tc / 8, 256>>>(rw);
    gemm_kernel<GM_MGU><<<dim3(22, 32, 8), 128, GSMEM>>>(nullptr);
    gemm_kernel<GM_MD><<<dim3(16, 32, 8), 128, GSMEM>>>(nullptr);

    // shared expert (SD fuses final residual -> writes d_out directly)
    gemm_kernel<GM_SGU><<<dim3(88, 32, 1), 128, GSMEM>>>(nullptr);
    sgate_kernel<<<Tc / 8, 256>>>(sgw);
    gemm_kernel<GM_SD><<<dim3(16, 32, 1), 128, GSMEM>>>((const float*)out);
}